// round 3
// baseline (speedup 1.0000x reference)
#include <cuda_runtime.h>
#include <cstdint>

#define R      128
#define R2     (R * R)
#define R3     (R * R * R)
#define BATCH  2
#define NV     7700
#define NSURF  6890
#define NT     30000
#define NBLK_SPLAT (BATCH * NSURF)

#define SIGMA  0.05f
#define EPS_W  0.001f
#define INV_2SIG2 (1.0f / (2.0f * SIGMA * SIGMA))   // 200.0
#define INV_R  (1.0f / 128.0f)

// Scratch: per-voxel accumulator (sem.rgb, wsum) and occupancy flag.
__device__ float4        g_acc[BATCH * R3];   // ~67 MB
__device__ unsigned char g_occ[BATCH * R3];   // ~4 MB

// ---------------------------------------------------------------------------
// 1) init: acc = (0,0,0,EPS_W), occ = 0
// ---------------------------------------------------------------------------
__global__ void init_kernel() {
    int i = blockIdx.x * blockDim.x + threadIdx.x;
    if (i < BATCH * R3) {
        g_acc[i] = make_float4(0.f, 0.f, 0.f, EPS_W);
        g_occ[i] = 0;
    }
}

// ---------------------------------------------------------------------------
// 2) tet occupancy: one thread per (batch, tet), 125 candidate voxels each
// ---------------------------------------------------------------------------
__global__ void tet_kernel(const float* __restrict__ verts,
                           const int*   __restrict__ tets) {
    int t = blockIdx.x * blockDim.x + threadIdx.x;
    if (t >= BATCH * NT) return;
    int b  = t / NT;
    int ti = t - b * NT;

    int i0 = tets[ti * 4 + 0];
    int i1 = tets[ti * 4 + 1];
    int i2 = tets[ti * 4 + 2];
    int i3 = tets[ti * 4 + 3];

    const float* vb = verts + (size_t)b * NV * 3;
    float ax_ = vb[i0 * 3 + 0], ay_ = vb[i0 * 3 + 1], az_ = vb[i0 * 3 + 2];
    float bx_ = vb[i1 * 3 + 0], by_ = vb[i1 * 3 + 1], bz_ = vb[i1 * 3 + 2];
    float cx_ = vb[i2 * 3 + 0], cy_ = vb[i2 * 3 + 1], cz_ = vb[i2 * 3 + 2];
    float dx_ = vb[i3 * 3 + 0], dy_ = vb[i3 * 3 + 1], dz_ = vb[i3 * 3 + 2];

    float e1x = bx_ - ax_, e1y = by_ - ay_, e1z = bz_ - az_;
    float e2x = cx_ - ax_, e2y = cy_ - ay_, e2z = cz_ - az_;
    float e3x = dx_ - ax_, e3y = dy_ - ay_, e3z = dz_ - az_;

    // c23 = e2 x e3
    float nx = e2y * e3z - e2z * e3y;
    float ny = e2z * e3x - e2x * e3z;
    float nz = e2x * e3y - e2y * e3x;
    float vol6 = e1x * nx + e1y * ny + e1z * nz;
    if (fabsf(vol6) <= 1e-12f) return;
    float iv = 1.0f / vol6;

    // anchor = floor(min over 4 verts * R)
    float mnx = fminf(fminf(ax_, bx_), fminf(cx_, dx_));
    float mny = fminf(fminf(ay_, by_), fminf(cy_, dy_));
    float mnz = fminf(fminf(az_, bz_), fminf(cz_, dz_));
    int anx = (int)floorf(mnx * (float)R);
    int any_ = (int)floorf(mny * (float)R);
    int anz = (int)floorf(mnz * (float)R);

    unsigned char* occ_b = g_occ + (size_t)b * R3;

    #pragma unroll 1
    for (int i = 0; i < 125; i++) {
        int ox = i / 25;
        int oy = (i / 5) % 5;
        int oz = i % 5;
        int x = anx + ox, y = any_ + oy, z = anz + oz;
        if ((unsigned)x >= R || (unsigned)y >= R || (unsigned)z >= R) continue;

        float px = ((float)x + 0.5f) * INV_R - ax_;
        float py = ((float)y + 0.5f) * INV_R - ay_;
        float pz = ((float)z + 0.5f) * INV_R - az_;

        // l1 = dot(p, c23) * iv
        float l1 = (px * nx + py * ny + pz * nz) * iv;
        // l2 = dot(cross(p, e3), e1) * iv   (matches reference arithmetic)
        float cpx = py * e3z - pz * e3y;
        float cpy = pz * e3x - px * e3z;
        float cpz = px * e3y - py * e3x;
        float l2 = (cpx * e1x + cpy * e1y + cpz * e1z) * iv;
        // l3 = dot(cross(e2, p), e1) * iv
        float cqx = e2y * pz - e2z * py;
        float cqy = e2z * px - e2x * pz;
        float cqz = e2x * py - e2y * px;
        float l3 = (cqx * e1x + cqy * e1y + cqz * e1z) * iv;

        if (l1 >= 0.f && l2 >= 0.f && l3 >= 0.f && (l1 + l2 + l3) <= 1.0f) {
            occ_b[(z * R + y) * R + x] = 1;   // benign race: all writers store 1
        }
    }
}

// ---------------------------------------------------------------------------
// 3) splat: one block per (batch, surface vertex); separable Gaussian weights
//    in shared; one red.global.add.v4.f32 per contribution.
// ---------------------------------------------------------------------------
__global__ void splat_kernel(const float* __restrict__ verts,
                             const float* __restrict__ code) {
    int v = blockIdx.x;                 // 0 .. BATCH*NSURF-1
    int b = v / NSURF;
    int s = v - b * NSURF;

    float vx = verts[((size_t)b * NV + s) * 3 + 0];
    float vy = verts[((size_t)b * NV + s) * 3 + 1];
    float vz = verts[((size_t)b * NV + s) * 3 + 2];
    float cr = code[((size_t)b * NSURF + s) * 3 + 0];
    float cg = code[((size_t)b * NSURF + s) * 3 + 1];
    float cb = code[((size_t)b * NSURF + s) * 3 + 2];

    int bx = (int)floorf(vx * (float)R);
    int by = (int)floorf(vy * (float)R);
    int bz = (int)floorf(vz * (float)R);

    __shared__ float wax[7], way[7], waz[7];
    int tid = threadIdx.x;
    if (tid < 21) {
        int axis = tid / 7;
        int o    = tid % 7;            // 0..6 -> offset o-3
        int base = (axis == 0) ? bx : (axis == 1) ? by : bz;
        float vc = (axis == 0) ? vx : (axis == 1) ? vy : vz;
        float d  = ((float)(base + o - 3) + 0.5f) * INV_R - vc;
        float w  = __expf(-d * d * INV_2SIG2);
        if (axis == 0)      wax[o] = w;
        else if (axis == 1) way[o] = w;
        else                waz[o] = w;
    }
    __syncthreads();

    float4* acc_b = g_acc + (size_t)b * R3;

    for (int i = tid; i < 343; i += blockDim.x) {
        int ox = i / 49;
        int oy = (i / 7) % 7;
        int oz = i % 7;
        int x = bx + ox - 3;
        int y = by + oy - 3;
        int z = bz + oz - 3;
        if ((unsigned)x < R && (unsigned)y < R && (unsigned)z < R) {
            float w = wax[ox] * way[oy] * waz[oz];
            float4* p = &acc_b[(z * R + y) * R + x];
            asm volatile("red.global.add.v4.f32 [%0], {%1, %2, %3, %4};"
                         :: "l"(p), "f"(w * cr), "f"(w * cg), "f"(w * cb), "f"(w)
                         : "memory");
        }
    }
}

// ---------------------------------------------------------------------------
// 4) finalize: out[b, c, z, y, x] = sem_c * occ / wsum
// ---------------------------------------------------------------------------
__global__ void final_kernel(float* __restrict__ out) {
    int i = blockIdx.x * blockDim.x + threadIdx.x;
    if (i >= BATCH * R3) return;
    int b = i >> 21;            // / R3
    int v = i & (R3 - 1);       // % R3

    float4 acc  = g_acc[i];
    float scale = g_occ[i] ? (1.0f / acc.w) : 0.0f;

    float* ob = out + (size_t)b * 3 * R3;
    ob[0 * R3 + v] = acc.x * scale;
    ob[1 * R3 + v] = acc.y * scale;
    ob[2 * R3 + v] = acc.z * scale;
}

// ---------------------------------------------------------------------------
extern "C" void kernel_launch(void* const* d_in, const int* in_sizes, int n_in,
                              void* d_out, int out_size) {
    const float* verts = (const float*)d_in[0];   // smpl_vertices (B, NV, 3)
    const float* code  = (const float*)d_in[1];   // vertex_code   (B, NSURF, 3)
    // d_in[2] = face_indices: dead code in the reference, unused.
    const int*   tets  = (const int*)  d_in[3];   // tet_indices   (NT, 4)
    float*       out   = (float*)d_out;           // (B, 3, R, R, R)

    init_kernel <<<(BATCH * R3 + 255) / 256, 256>>>();
    tet_kernel  <<<(BATCH * NT + 127) / 128, 128>>>(verts, tets);
    splat_kernel<<<NBLK_SPLAT, 128>>>(verts, code);
    final_kernel<<<(BATCH * R3 + 255) / 256, 256>>>(out);
}